// round 2
// baseline (speedup 1.0000x reference)
#include <cuda_runtime.h>
#include <cuda_bf16.h>
#include <math.h>

// GCN: out = log_softmax( spmm(adj, relu(spmm(adj, x@W1)+b1) @ W2) + b2 )
// CSR-by-dst build (int atomics only), gather-style segment sums.
// R2: f32x2-packed 8x8-microtile GEMM1, int2-packed CSR payload,
//     4x-unrolled spMM gathers for MLP.

#define MAXN 100000
#define MAXE 1600000

__device__ int   g_off[MAXN];            // counts -> starts -> ends
__device__ int2  g_csr[MAXE];            // (src, val bits)
__device__ float g_support1[(size_t)MAXN * 64];
__device__ float g_h[(size_t)MAXN * 64];
__device__ float g_support2[(size_t)MAXN * 16];

// ------------------------------------------------------------- f32x2 helpers
__device__ __forceinline__ unsigned long long pack2(float lo, float hi) {
    unsigned long long r;
    asm("mov.b64 %0, {%1, %2};" : "=l"(r) : "f"(lo), "f"(hi));
    return r;
}
__device__ __forceinline__ void fma2(unsigned long long& d,
                                     unsigned long long a,
                                     unsigned long long b) {
    asm("fma.rn.f32x2 %0, %1, %2, %0;" : "+l"(d) : "l"(a), "l"(b));
}
__device__ __forceinline__ float2 unpack2(unsigned long long v) {
    float2 r;
    asm("mov.b64 {%0, %1}, %2;" : "=f"(r.x), "=f"(r.y) : "l"(v));
    return r;
}

// ---------------------------------------------------------------- CSR build
__global__ void zero_off_kernel(int N) {
    int i = (blockIdx.x * blockDim.x + threadIdx.x) * 4;
    if (i + 4 <= N) {
        *(int4*)&g_off[i] = make_int4(0, 0, 0, 0);
    } else {
        for (int j = i; j < N; j++) g_off[j] = 0;
    }
}

__global__ void hist_kernel(const int* __restrict__ dst, int E) {
    int i = (blockIdx.x * blockDim.x + threadIdx.x) * 4;
    if (i + 4 <= E) {
        int4 d = *(const int4*)(dst + i);
        atomicAdd(&g_off[d.x], 1);
        atomicAdd(&g_off[d.y], 1);
        atomicAdd(&g_off[d.z], 1);
        atomicAdd(&g_off[d.w], 1);
    } else {
        for (int j = i; j < E; j++) atomicAdd(&g_off[dst[j]], 1);
    }
}

// Single-block exclusive scan over g_off[0..N): counts -> row starts.
__global__ void scan_kernel(int N) {
    __shared__ int warp_sums[32];
    int t = threadIdx.x;                      // 1024 threads
    int chunk = (N + 1023) >> 10;
    int begin = t * chunk;
    int end = min(begin + chunk, N);

    int local = 0;
    for (int i = begin; i < end; i++) local += g_off[i];

    int lane = t & 31, w = t >> 5;
    int v = local;
    #pragma unroll
    for (int d = 1; d < 32; d <<= 1) {
        int n = __shfl_up_sync(0xFFFFFFFFu, v, d);
        if (lane >= d) v += n;
    }
    if (lane == 31) warp_sums[w] = v;
    __syncthreads();
    if (w == 0) {
        int s = warp_sums[lane];
        #pragma unroll
        for (int d = 1; d < 32; d <<= 1) {
            int n = __shfl_up_sync(0xFFFFFFFFu, s, d);
            if (lane >= d) s += n;
        }
        warp_sums[lane] = s;
    }
    __syncthreads();
    int excl = v - local + (w ? warp_sums[w - 1] : 0);

    int run = excl;
    for (int i = begin; i < end; i++) {
        int c = g_off[i];
        g_off[i] = run;
        run += c;
    }
}

// Scatter edges; bumps g_off[dst] from start to end (row i = [off[i-1], off[i])).
__global__ void scatter_kernel(const int* __restrict__ src,
                               const int* __restrict__ dst,
                               const float* __restrict__ val, int E) {
    int i = (blockIdx.x * blockDim.x + threadIdx.x) * 4;
    if (i + 4 <= E) {
        int4   s = *(const int4*)(src + i);
        int4   d = *(const int4*)(dst + i);
        float4 v = *(const float4*)(val + i);
        int p0 = atomicAdd(&g_off[d.x], 1);
        int p1 = atomicAdd(&g_off[d.y], 1);
        int p2 = atomicAdd(&g_off[d.z], 1);
        int p3 = atomicAdd(&g_off[d.w], 1);
        g_csr[p0] = make_int2(s.x, __float_as_int(v.x));
        g_csr[p1] = make_int2(s.y, __float_as_int(v.y));
        g_csr[p2] = make_int2(s.z, __float_as_int(v.z));
        g_csr[p3] = make_int2(s.w, __float_as_int(v.w));
    } else {
        for (int j = i; j < E; j++) {
            int p = atomicAdd(&g_off[dst[j]], 1);
            g_csr[p] = make_int2(src[j], __float_as_int(val[j]));
        }
    }
}

// ---------------------------------------------------------------- GEMM1
// support1[N,64] = x[N,256] @ W1[256,64].
// BM=128, BN=64, BK=16, 128 threads, 8x8 microtile, f32x2 packed FMA.
__global__ void gemm1_kernel(const float* __restrict__ x,
                             const float* __restrict__ W1, int N) {
    __shared__ float As[16][132];   // [k][m], padded
    __shared__ float Bs[16][64];    // [k][n]

    int tid = threadIdx.x;          // 128
    int m0 = blockIdx.x * 128;
    int tx = tid & 7, ty = tid >> 3;
    int tm = ty << 3;               // 0..120
    int tn = tx << 3;               // 0..56

    int arow = tid >> 2;            // 0..31
    int acol = (tid & 3) << 2;      // 0,4,8,12
    int brow = tid >> 4;            // 0..7
    int bcol = (tid & 15) << 2;     // 0..60

    unsigned long long acc[4][8] = {};  // [row-pair][col], zero bits == (0,0)

    for (int k0 = 0; k0 < 256; k0 += 16) {
        #pragma unroll
        for (int p = 0; p < 4; p++) {
            int r = arow + (p << 5);
            int gr = m0 + r;
            float4 av = make_float4(0.f, 0.f, 0.f, 0.f);
            if (gr < N)
                av = *(const float4*)(x + (size_t)gr * 256 + k0 + acol);
            As[acol + 0][r] = av.x;
            As[acol + 1][r] = av.y;
            As[acol + 2][r] = av.z;
            As[acol + 3][r] = av.w;
        }
        #pragma unroll
        for (int p = 0; p < 2; p++) {
            int kr = brow + (p << 3);
            *(float4*)&Bs[kr][bcol] =
                *(const float4*)(W1 + (size_t)(k0 + kr) * 64 + bcol);
        }
        __syncthreads();

        #pragma unroll
        for (int k = 0; k < 16; k++) {
            union { float4 f; unsigned long long u[2]; } a0, a1, b0, b1;
            a0.f = *(const float4*)&As[k][tm];
            a1.f = *(const float4*)&As[k][tm + 4];
            b0.f = *(const float4*)&Bs[k][tn];
            b1.f = *(const float4*)&Bs[k][tn + 4];

            unsigned long long ap0 = a0.u[0], ap1 = a0.u[1];
            unsigned long long ap2 = a1.u[0], ap3 = a1.u[1];

            float bsc[8] = { b0.f.x, b0.f.y, b0.f.z, b0.f.w,
                             b1.f.x, b1.f.y, b1.f.z, b1.f.w };
            #pragma unroll
            for (int j = 0; j < 8; j++) {
                unsigned long long bp = pack2(bsc[j], bsc[j]);
                fma2(acc[0][j], ap0, bp);
                fma2(acc[1][j], ap1, bp);
                fma2(acc[2][j], ap2, bp);
                fma2(acc[3][j], ap3, bp);
            }
        }
        __syncthreads();
    }

    #pragma unroll
    for (int rp = 0; rp < 4; rp++) {
        float lo[8], hi[8];
        #pragma unroll
        for (int j = 0; j < 8; j++) {
            float2 v = unpack2(acc[rp][j]);
            lo[j] = v.x; hi[j] = v.y;
        }
        int r0 = m0 + tm + (rp << 1);
        int r1 = r0 + 1;
        if (r0 < N) {
            *(float4*)&g_support1[(size_t)r0 * 64 + tn] =
                make_float4(lo[0], lo[1], lo[2], lo[3]);
            *(float4*)&g_support1[(size_t)r0 * 64 + tn + 4] =
                make_float4(lo[4], lo[5], lo[6], lo[7]);
        }
        if (r1 < N) {
            *(float4*)&g_support1[(size_t)r1 * 64 + tn] =
                make_float4(hi[0], hi[1], hi[2], hi[3]);
            *(float4*)&g_support1[(size_t)r1 * 64 + tn + 4] =
                make_float4(hi[4], hi[5], hi[6], hi[7]);
        }
    }
}

// ---------------------------------------------------------------- spMM1
// h[i,:] = relu( sum_{e in row i} w_e * support1[src_e,:] + b1 )
// 16 threads per node, one float4 each; edge loop unrolled x4 for MLP.
__global__ void spmm1_kernel(const float* __restrict__ b1, int N) {
    int t = blockIdx.x * blockDim.x + threadIdx.x;
    int node = t >> 4;
    if (node >= N) return;
    int c = (t & 15) << 2;

    int start = node ? g_off[node - 1] : 0;
    int end = g_off[node];

    float4 acc = make_float4(0.f, 0.f, 0.f, 0.f);
    int e = start;
    for (; e + 4 <= end; e += 4) {
        int2 e0 = g_csr[e], e1 = g_csr[e + 1], e2 = g_csr[e + 2], e3 = g_csr[e + 3];
        float4 v0 = *(const float4*)&g_support1[(size_t)e0.x * 64 + c];
        float4 v1 = *(const float4*)&g_support1[(size_t)e1.x * 64 + c];
        float4 v2 = *(const float4*)&g_support1[(size_t)e2.x * 64 + c];
        float4 v3 = *(const float4*)&g_support1[(size_t)e3.x * 64 + c];
        float w0 = __int_as_float(e0.y), w1 = __int_as_float(e1.y);
        float w2 = __int_as_float(e2.y), w3 = __int_as_float(e3.y);
        acc.x = fmaf(w0, v0.x, acc.x); acc.y = fmaf(w0, v0.y, acc.y);
        acc.z = fmaf(w0, v0.z, acc.z); acc.w = fmaf(w0, v0.w, acc.w);
        acc.x = fmaf(w1, v1.x, acc.x); acc.y = fmaf(w1, v1.y, acc.y);
        acc.z = fmaf(w1, v1.z, acc.z); acc.w = fmaf(w1, v1.w, acc.w);
        acc.x = fmaf(w2, v2.x, acc.x); acc.y = fmaf(w2, v2.y, acc.y);
        acc.z = fmaf(w2, v2.z, acc.z); acc.w = fmaf(w2, v2.w, acc.w);
        acc.x = fmaf(w3, v3.x, acc.x); acc.y = fmaf(w3, v3.y, acc.y);
        acc.z = fmaf(w3, v3.z, acc.z); acc.w = fmaf(w3, v3.w, acc.w);
    }
    for (; e < end; e++) {
        int2 ed = g_csr[e];
        float w = __int_as_float(ed.y);
        float4 v = *(const float4*)&g_support1[(size_t)ed.x * 64 + c];
        acc.x = fmaf(w, v.x, acc.x); acc.y = fmaf(w, v.y, acc.y);
        acc.z = fmaf(w, v.z, acc.z); acc.w = fmaf(w, v.w, acc.w);
    }
    float4 bb = *(const float4*)&b1[c];
    acc.x = fmaxf(acc.x + bb.x, 0.f);
    acc.y = fmaxf(acc.y + bb.y, 0.f);
    acc.z = fmaxf(acc.z + bb.z, 0.f);
    acc.w = fmaxf(acc.w + bb.w, 0.f);
    *(float4*)&g_h[(size_t)node * 64 + c] = acc;
}

// ---------------------------------------------------------------- GEMM2
// support2[N,16] = h[N,64] @ W2[64,16]. 4 threads per node (k-split),
// quad shuffle reduce.
__global__ void gemm2_kernel(const float* __restrict__ W2, int N) {
    __shared__ float w2s[64 * 16];
    int tid = threadIdx.x;  // 256
    for (int i = tid; i < 64 * 16; i += 256) w2s[i] = W2[i];
    __syncthreads();

    int t = blockIdx.x * 256 + tid;
    int node = t >> 2;
    int part = t & 3;

    float acc[16] = {};
    if (node < N) {
        const float* hrow = &g_h[(size_t)node * 64 + part * 16];
        #pragma unroll
        for (int kk = 0; kk < 16; kk++) {
            float hv = hrow[kk];
            int k = part * 16 + kk;
            #pragma unroll
            for (int j = 0; j < 16; j++)
                acc[j] = fmaf(hv, w2s[k * 16 + j], acc[j]);
        }
    }
    #pragma unroll
    for (int j = 0; j < 16; j++) {
        acc[j] += __shfl_xor_sync(0xFFFFFFFFu, acc[j], 1);
        acc[j] += __shfl_xor_sync(0xFFFFFFFFu, acc[j], 2);
    }
    if (node < N && part == 0) {
        #pragma unroll
        for (int j = 0; j < 16; j += 4)
            *(float4*)&g_support2[(size_t)node * 16 + j] =
                make_float4(acc[j], acc[j + 1], acc[j + 2], acc[j + 3]);
    }
}

// ------------------------------------------------ spMM2 + log_softmax fused
// 4 threads per node, one float4 of the 16 classes each.
__global__ void spmm2_kernel(const float* __restrict__ b2,
                             float* __restrict__ out, int N) {
    int t = blockIdx.x * blockDim.x + threadIdx.x;
    int node = t >> 2;
    int q = (t & 3) << 2;

    float4 acc = make_float4(0.f, 0.f, 0.f, 0.f);
    if (node < N) {
        int start = node ? g_off[node - 1] : 0;
        int end = g_off[node];
        int e = start;
        for (; e + 4 <= end; e += 4) {
            int2 e0 = g_csr[e], e1 = g_csr[e + 1], e2 = g_csr[e + 2], e3 = g_csr[e + 3];
            float4 v0 = *(const float4*)&g_support2[(size_t)e0.x * 16 + q];
            float4 v1 = *(const float4*)&g_support2[(size_t)e1.x * 16 + q];
            float4 v2 = *(const float4*)&g_support2[(size_t)e2.x * 16 + q];
            float4 v3 = *(const float4*)&g_support2[(size_t)e3.x * 16 + q];
            float w0 = __int_as_float(e0.y), w1 = __int_as_float(e1.y);
            float w2 = __int_as_float(e2.y), w3 = __int_as_float(e3.y);
            acc.x = fmaf(w0, v0.x, acc.x); acc.y = fmaf(w0, v0.y, acc.y);
            acc.z = fmaf(w0, v0.z, acc.z); acc.w = fmaf(w0, v0.w, acc.w);
            acc.x = fmaf(w1, v1.x, acc.x); acc.y = fmaf(w1, v1.y, acc.y);
            acc.z = fmaf(w1, v1.z, acc.z); acc.w = fmaf(w1, v1.w, acc.w);
            acc.x = fmaf(w2, v2.x, acc.x); acc.y = fmaf(w2, v2.y, acc.y);
            acc.z = fmaf(w2, v2.z, acc.z); acc.w = fmaf(w2, v2.w, acc.w);
            acc.x = fmaf(w3, v3.x, acc.x); acc.y = fmaf(w3, v3.y, acc.y);
            acc.z = fmaf(w3, v3.z, acc.z); acc.w = fmaf(w3, v3.w, acc.w);
        }
        for (; e < end; e++) {
            int2 ed = g_csr[e];
            float w = __int_as_float(ed.y);
            float4 v = *(const float4*)&g_support2[(size_t)ed.x * 16 + q];
            acc.x = fmaf(w, v.x, acc.x); acc.y = fmaf(w, v.y, acc.y);
            acc.z = fmaf(w, v.z, acc.z); acc.w = fmaf(w, v.w, acc.w);
        }
        float4 bb = *(const float4*)&b2[q];
        acc.x += bb.x; acc.y += bb.y; acc.z += bb.z; acc.w += bb.w;
    }

    float m = fmaxf(fmaxf(acc.x, acc.y), fmaxf(acc.z, acc.w));
    m = fmaxf(m, __shfl_xor_sync(0xFFFFFFFFu, m, 1));
    m = fmaxf(m, __shfl_xor_sync(0xFFFFFFFFu, m, 2));
    float s = expf(acc.x - m) + expf(acc.y - m) + expf(acc.z - m) + expf(acc.w - m);
    s += __shfl_xor_sync(0xFFFFFFFFu, s, 1);
    s += __shfl_xor_sync(0xFFFFFFFFu, s, 2);
    float lse = m + logf(s);

    if (node < N) {
        *(float4*)&out[(size_t)node * 16 + q] =
            make_float4(acc.x - lse, acc.y - lse, acc.z - lse, acc.w - lse);
    }
}

// ---------------------------------------------------------------- launch
extern "C" void kernel_launch(void* const* d_in, const int* in_sizes, int n_in,
                              void* d_out, int out_size) {
    const float* x    = (const float*)d_in[0];
    const int*   esrc = (const int*)d_in[1];
    const int*   edst = (const int*)d_in[2];
    const float* ev   = (const float*)d_in[3];
    const float* W1   = (const float*)d_in[4];
    const float* b1   = (const float*)d_in[5];
    const float* W2   = (const float*)d_in[6];
    const float* b2   = (const float*)d_in[7];
    float* out = (float*)d_out;

    int E = in_sizes[1];
    int N = in_sizes[0] / 256;

    int eq = (E + 3) / 4;
    int nq = (N + 3) / 4;

    // CSR build
    zero_off_kernel<<<(nq + 255) / 256, 256>>>(N);
    hist_kernel<<<(eq + 255) / 256, 256>>>(edst, E);
    scan_kernel<<<1, 1024>>>(N);
    scatter_kernel<<<(eq + 255) / 256, 256>>>(esrc, edst, ev, E);

    // Layer 1
    gemm1_kernel<<<(N + 127) / 128, 128>>>(x, W1, N);
    spmm1_kernel<<<(N * 16 + 255) / 256, 256>>>(b1, N);

    // Layer 2 + log_softmax
    gemm2_kernel<<<(N * 4 + 255) / 256, 256>>>(W2, N);
    spmm2_kernel<<<(N * 4 + 255) / 256, 256>>>(b2, out, N);
}

// round 3
// speedup vs baseline: 1.5864x; 1.5864x over previous
#include <cuda_runtime.h>
#include <cuda_bf16.h>
#include <math.h>

// GCN: out = log_softmax( spmm(adj, relu(spmm(adj, x@W1)+b1) @ W2) + b2 )
// R3: multi-block scan (was single-block = 1 SM), gemm2 fused into spmm1
//     epilogue (g_h eliminated), gemm1 moved to profiled launch slot.

#define MAXN 100000
#define MAXE 1600000
#define SCAN_BLK 256

__device__ int   g_off[MAXN];            // counts -> starts -> ends
__device__ int   g_bsum[1024];           // block sums for scan
__device__ int2  g_csr[MAXE];            // (src, val bits)
__device__ float g_support1[(size_t)MAXN * 64];
__device__ float g_support2[(size_t)MAXN * 16];

// ------------------------------------------------------------- f32x2 helpers
__device__ __forceinline__ unsigned long long pack2(float lo, float hi) {
    unsigned long long r;
    asm("mov.b64 %0, {%1, %2};" : "=l"(r) : "f"(lo), "f"(hi));
    return r;
}
__device__ __forceinline__ void fma2(unsigned long long& d,
                                     unsigned long long a,
                                     unsigned long long b) {
    asm("fma.rn.f32x2 %0, %1, %2, %0;" : "+l"(d) : "l"(a), "l"(b));
}
__device__ __forceinline__ float2 unpack2(unsigned long long v) {
    float2 r;
    asm("mov.b64 {%0, %1}, %2;" : "=f"(r.x), "=f"(r.y) : "l"(v));
    return r;
}

// ---------------------------------------------------------------- CSR build
__global__ void zero_off_kernel(int N) {
    int i = (blockIdx.x * blockDim.x + threadIdx.x) * 4;
    if (i + 4 <= N) {
        *(int4*)&g_off[i] = make_int4(0, 0, 0, 0);
    } else {
        for (int j = i; j < N; j++) g_off[j] = 0;
    }
}

__global__ void hist_kernel(const int* __restrict__ dst, int E) {
    int i = (blockIdx.x * blockDim.x + threadIdx.x) * 4;
    if (i + 4 <= E) {
        int4 d = *(const int4*)(dst + i);
        atomicAdd(&g_off[d.x], 1);
        atomicAdd(&g_off[d.y], 1);
        atomicAdd(&g_off[d.z], 1);
        atomicAdd(&g_off[d.w], 1);
    } else {
        for (int j = i; j < E; j++) atomicAdd(&g_off[dst[j]], 1);
    }
}

// scan phase A: per-block sums of counts
__global__ void scan_a_kernel(int N) {
    __shared__ int ws[8];
    int i = blockIdx.x * SCAN_BLK + threadIdx.x;
    int v = (i < N) ? g_off[i] : 0;
    int lane = threadIdx.x & 31, w = threadIdx.x >> 5;
    int s = v;
    #pragma unroll
    for (int d = 16; d > 0; d >>= 1) s += __shfl_xor_sync(0xFFFFFFFFu, s, d);
    if (lane == 0) ws[w] = s;
    __syncthreads();
    if (threadIdx.x == 0) {
        int t = 0;
        #pragma unroll
        for (int k = 0; k < 8; k++) t += ws[k];
        g_bsum[blockIdx.x] = t;
    }
}

// scan phase B: single-block exclusive scan of block sums (nb <= 1024)
__global__ void scan_b_kernel(int nb) {
    __shared__ int wsum[32];
    int t = threadIdx.x;  // 1024
    int v = (t < nb) ? g_bsum[t] : 0;
    int lane = t & 31, w = t >> 5;
    int incl = v;
    #pragma unroll
    for (int d = 1; d < 32; d <<= 1) {
        int n = __shfl_up_sync(0xFFFFFFFFu, incl, d);
        if (lane >= d) incl += n;
    }
    if (lane == 31) wsum[w] = incl;
    __syncthreads();
    if (w == 0) {
        int s = wsum[lane];
        #pragma unroll
        for (int d = 1; d < 32; d <<= 1) {
            int n = __shfl_up_sync(0xFFFFFFFFu, s, d);
            if (lane >= d) s += n;
        }
        wsum[lane] = s;
    }
    __syncthreads();
    int excl = incl - v + (w ? wsum[w - 1] : 0);
    if (t < nb) g_bsum[t] = excl;
}

// scan phase C: per-block exclusive scan + base -> row starts
__global__ void scan_c_kernel(int N) {
    __shared__ int ws[8];
    int i = blockIdx.x * SCAN_BLK + threadIdx.x;
    int v = (i < N) ? g_off[i] : 0;
    int lane = threadIdx.x & 31, w = threadIdx.x >> 5;
    int incl = v;
    #pragma unroll
    for (int d = 1; d < 32; d <<= 1) {
        int n = __shfl_up_sync(0xFFFFFFFFu, incl, d);
        if (lane >= d) incl += n;
    }
    if (lane == 31) ws[w] = incl;
    __syncthreads();
    if (w == 0 && lane < 8) {
        int s = ws[lane];
        #pragma unroll
        for (int d = 1; d < 8; d <<= 1) {
            int n = __shfl_up_sync(0x000000FFu, s, d);
            if (lane >= d) s += n;
        }
        ws[lane] = s;
    }
    __syncthreads();
    int excl = incl - v + (w ? ws[w - 1] : 0);
    if (i < N) g_off[i] = g_bsum[blockIdx.x] + excl;
}

// Scatter edges; bumps g_off[dst] from start to end (row i = [off[i-1], off[i])).
__global__ void scatter_kernel(const int* __restrict__ src,
                               const int* __restrict__ dst,
                               const float* __restrict__ val, int E) {
    int i = (blockIdx.x * blockDim.x + threadIdx.x) * 4;
    if (i + 4 <= E) {
        int4   s = *(const int4*)(src + i);
        int4   d = *(const int4*)(dst + i);
        float4 v = *(const float4*)(val + i);
        int p0 = atomicAdd(&g_off[d.x], 1);
        int p1 = atomicAdd(&g_off[d.y], 1);
        int p2 = atomicAdd(&g_off[d.z], 1);
        int p3 = atomicAdd(&g_off[d.w], 1);
        g_csr[p0] = make_int2(s.x, __float_as_int(v.x));
        g_csr[p1] = make_int2(s.y, __float_as_int(v.y));
        g_csr[p2] = make_int2(s.z, __float_as_int(v.z));
        g_csr[p3] = make_int2(s.w, __float_as_int(v.w));
    } else {
        for (int j = i; j < E; j++) {
            int p = atomicAdd(&g_off[dst[j]], 1);
            g_csr[p] = make_int2(src[j], __float_as_int(val[j]));
        }
    }
}

// ---------------------------------------------------------------- GEMM1
// support1[N,64] = x[N,256] @ W1[256,64].
// BM=128, BN=64, BK=16, 128 threads, 8x8 microtile, f32x2 packed FMA.
__global__ void gemm1_kernel(const float* __restrict__ x,
                             const float* __restrict__ W1, int N) {
    __shared__ float As[16][132];   // [k][m], padded
    __shared__ float Bs[16][64];    // [k][n]

    int tid = threadIdx.x;          // 128
    int m0 = blockIdx.x * 128;
    int tx = tid & 7, ty = tid >> 3;
    int tm = ty << 3;               // 0..120
    int tn = tx << 3;               // 0..56

    int arow = tid >> 2;            // 0..31
    int acol = (tid & 3) << 2;      // 0,4,8,12
    int brow = tid >> 4;            // 0..7
    int bcol = (tid & 15) << 2;     // 0..60

    unsigned long long acc[4][8] = {};  // [row-pair][col]

    for (int k0 = 0; k0 < 256; k0 += 16) {
        #pragma unroll
        for (int p = 0; p < 4; p++) {
            int r = arow + (p << 5);
            int gr = m0 + r;
            float4 av = make_float4(0.f, 0.f, 0.f, 0.f);
            if (gr < N)
                av = *(const float4*)(x + (size_t)gr * 256 + k0 + acol);
            As[acol + 0][r] = av.x;
            As[acol + 1][r] = av.y;
            As[acol + 2][r] = av.z;
            As[acol + 3][r] = av.w;
        }
        #pragma unroll
        for (int p = 0; p < 2; p++) {
            int kr = brow + (p << 3);
            *(float4*)&Bs[kr][bcol] =
                *(const float4*)(W1 + (size_t)(k0 + kr) * 64 + bcol);
        }
        __syncthreads();

        #pragma unroll
        for (int k = 0; k < 16; k++) {
            union { float4 f; unsigned long long u[2]; } a0, a1, b0, b1;
            a0.f = *(const float4*)&As[k][tm];
            a1.f = *(const float4*)&As[k][tm + 4];
            b0.f = *(const float4*)&Bs[k][tn];
            b1.f = *(const float4*)&Bs[k][tn + 4];

            unsigned long long ap0 = a0.u[0], ap1 = a0.u[1];
            unsigned long long ap2 = a1.u[0], ap3 = a1.u[1];

            float bsc[8] = { b0.f.x, b0.f.y, b0.f.z, b0.f.w,
                             b1.f.x, b1.f.y, b1.f.z, b1.f.w };
            #pragma unroll
            for (int j = 0; j < 8; j++) {
                unsigned long long bp = pack2(bsc[j], bsc[j]);
                fma2(acc[0][j], ap0, bp);
                fma2(acc[1][j], ap1, bp);
                fma2(acc[2][j], ap2, bp);
                fma2(acc[3][j], ap3, bp);
            }
        }
        __syncthreads();
    }

    #pragma unroll
    for (int rp = 0; rp < 4; rp++) {
        float lo[8], hi[8];
        #pragma unroll
        for (int j = 0; j < 8; j++) {
            float2 v = unpack2(acc[rp][j]);
            lo[j] = v.x; hi[j] = v.y;
        }
        int r0 = m0 + tm + (rp << 1);
        int r1 = r0 + 1;
        if (r0 < N) {
            *(float4*)&g_support1[(size_t)r0 * 64 + tn] =
                make_float4(lo[0], lo[1], lo[2], lo[3]);
            *(float4*)&g_support1[(size_t)r0 * 64 + tn + 4] =
                make_float4(lo[4], lo[5], lo[6], lo[7]);
        }
        if (r1 < N) {
            *(float4*)&g_support1[(size_t)r1 * 64 + tn] =
                make_float4(hi[0], hi[1], hi[2], hi[3]);
            *(float4*)&g_support1[(size_t)r1 * 64 + tn + 4] =
                make_float4(hi[4], hi[5], hi[6], hi[7]);
        }
    }
}

// ---------------------------------------- spMM1 + (relu,b1) + GEMM2 fused
// 16 threads per node; h row stays in registers; support2 = relu(h)@W2
// computed via 16-lane butterfly reduce. g_h never touches memory.
__global__ void spmm1_gemm2_kernel(const float* __restrict__ b1,
                                   const float* __restrict__ W2, int N) {
    __shared__ float w2t[16][68];   // transposed W2, padded
    int tid = threadIdx.x;          // 256
    for (int i = tid; i < 64 * 16; i += 256) {
        int k = i >> 4, j = i & 15;
        w2t[j][k] = W2[i];
    }
    __syncthreads();

    int t = blockIdx.x * 256 + tid;
    int node = t >> 4;
    int c = (t & 15) << 2;
    bool valid = (node < N);

    float4 acc = make_float4(0.f, 0.f, 0.f, 0.f);
    if (valid) {
        int start = node ? g_off[node - 1] : 0;
        int end = g_off[node];
        int e = start;
        for (; e + 4 <= end; e += 4) {
            int2 e0 = g_csr[e], e1 = g_csr[e + 1], e2 = g_csr[e + 2], e3 = g_csr[e + 3];
            float4 v0 = *(const float4*)&g_support1[(size_t)e0.x * 64 + c];
            float4 v1 = *(const float4*)&g_support1[(size_t)e1.x * 64 + c];
            float4 v2 = *(const float4*)&g_support1[(size_t)e2.x * 64 + c];
            float4 v3 = *(const float4*)&g_support1[(size_t)e3.x * 64 + c];
            float w0 = __int_as_float(e0.y), w1 = __int_as_float(e1.y);
            float w2 = __int_as_float(e2.y), w3 = __int_as_float(e3.y);
            acc.x = fmaf(w0, v0.x, acc.x); acc.y = fmaf(w0, v0.y, acc.y);
            acc.z = fmaf(w0, v0.z, acc.z); acc.w = fmaf(w0, v0.w, acc.w);
            acc.x = fmaf(w1, v1.x, acc.x); acc.y = fmaf(w1, v1.y, acc.y);
            acc.z = fmaf(w1, v1.z, acc.z); acc.w = fmaf(w1, v1.w, acc.w);
            acc.x = fmaf(w2, v2.x, acc.x); acc.y = fmaf(w2, v2.y, acc.y);
            acc.z = fmaf(w2, v2.z, acc.z); acc.w = fmaf(w2, v2.w, acc.w);
            acc.x = fmaf(w3, v3.x, acc.x); acc.y = fmaf(w3, v3.y, acc.y);
            acc.z = fmaf(w3, v3.z, acc.z); acc.w = fmaf(w3, v3.w, acc.w);
        }
        for (; e < end; e++) {
            int2 ed = g_csr[e];
            float w = __int_as_float(ed.y);
            float4 v = *(const float4*)&g_support1[(size_t)ed.x * 64 + c];
            acc.x = fmaf(w, v.x, acc.x); acc.y = fmaf(w, v.y, acc.y);
            acc.z = fmaf(w, v.z, acc.z); acc.w = fmaf(w, v.w, acc.w);
        }
        float4 bb = *(const float4*)&b1[c];
        acc.x = fmaxf(acc.x + bb.x, 0.f);
        acc.y = fmaxf(acc.y + bb.y, 0.f);
        acc.z = fmaxf(acc.z + bb.z, 0.f);
        acc.w = fmaxf(acc.w + bb.w, 0.f);
    }

    // gemm2 epilogue: partial[j] = sum over this thread's 4 features
    float part[16];
    #pragma unroll
    for (int j = 0; j < 16; j++) {
        float s = acc.x * w2t[j][c];
        s = fmaf(acc.y, w2t[j][c + 1], s);
        s = fmaf(acc.z, w2t[j][c + 2], s);
        s = fmaf(acc.w, w2t[j][c + 3], s);
        part[j] = s;
    }
    // butterfly reduce across the 16 lanes of this node group
    #pragma unroll
    for (int d = 1; d < 16; d <<= 1) {
        #pragma unroll
        for (int j = 0; j < 16; j++)
            part[j] += __shfl_xor_sync(0xFFFFFFFFu, part[j], d);
    }
    int sub = t & 15;
    if (valid && sub < 4) {
        *(float4*)&g_support2[(size_t)node * 16 + sub * 4] =
            make_float4(part[sub * 4], part[sub * 4 + 1],
                        part[sub * 4 + 2], part[sub * 4 + 3]);
    }
}

// ------------------------------------------------ spMM2 + log_softmax fused
__global__ void spmm2_kernel(const float* __restrict__ b2,
                             float* __restrict__ out, int N) {
    int t = blockIdx.x * blockDim.x + threadIdx.x;
    int node = t >> 2;
    int q = (t & 3) << 2;

    float4 acc = make_float4(0.f, 0.f, 0.f, 0.f);
    if (node < N) {
        int start = node ? g_off[node - 1] : 0;
        int end = g_off[node];
        int e = start;
        for (; e + 4 <= end; e += 4) {
            int2 e0 = g_csr[e], e1 = g_csr[e + 1], e2 = g_csr[e + 2], e3 = g_csr[e + 3];
            float4 v0 = *(const float4*)&g_support2[(size_t)e0.x * 16 + q];
            float4 v1 = *(const float4*)&g_support2[(size_t)e1.x * 16 + q];
            float4 v2 = *(const float4*)&g_support2[(size_t)e2.x * 16 + q];
            float4 v3 = *(const float4*)&g_support2[(size_t)e3.x * 16 + q];
            float w0 = __int_as_float(e0.y), w1 = __int_as_float(e1.y);
            float w2 = __int_as_float(e2.y), w3 = __int_as_float(e3.y);
            acc.x = fmaf(w0, v0.x, acc.x); acc.y = fmaf(w0, v0.y, acc.y);
            acc.z = fmaf(w0, v0.z, acc.z); acc.w = fmaf(w0, v0.w, acc.w);
            acc.x = fmaf(w1, v1.x, acc.x); acc.y = fmaf(w1, v1.y, acc.y);
            acc.z = fmaf(w1, v1.z, acc.z); acc.w = fmaf(w1, v1.w, acc.w);
            acc.x = fmaf(w2, v2.x, acc.x); acc.y = fmaf(w2, v2.y, acc.y);
            acc.z = fmaf(w2, v2.z, acc.z); acc.w = fmaf(w2, v2.w, acc.w);
            acc.x = fmaf(w3, v3.x, acc.x); acc.y = fmaf(w3, v3.y, acc.y);
            acc.z = fmaf(w3, v3.z, acc.z); acc.w = fmaf(w3, v3.w, acc.w);
        }
        for (; e < end; e++) {
            int2 ed = g_csr[e];
            float w = __int_as_float(ed.y);
            float4 v = *(const float4*)&g_support2[(size_t)ed.x * 16 + q];
            acc.x = fmaf(w, v.x, acc.x); acc.y = fmaf(w, v.y, acc.y);
            acc.z = fmaf(w, v.z, acc.z); acc.w = fmaf(w, v.w, acc.w);
        }
        float4 bb = *(const float4*)&b2[q];
        acc.x += bb.x; acc.y += bb.y; acc.z += bb.z; acc.w += bb.w;
    }

    float m = fmaxf(fmaxf(acc.x, acc.y), fmaxf(acc.z, acc.w));
    m = fmaxf(m, __shfl_xor_sync(0xFFFFFFFFu, m, 1));
    m = fmaxf(m, __shfl_xor_sync(0xFFFFFFFFu, m, 2));
    float s = expf(acc.x - m) + expf(acc.y - m) + expf(acc.z - m) + expf(acc.w - m);
    s += __shfl_xor_sync(0xFFFFFFFFu, s, 1);
    s += __shfl_xor_sync(0xFFFFFFFFu, s, 2);
    float lse = m + logf(s);

    if (node < N) {
        *(float4*)&out[(size_t)node * 16 + q] =
            make_float4(acc.x - lse, acc.y - lse, acc.z - lse, acc.w - lse);
    }
}

// ---------------------------------------------------------------- launch
extern "C" void kernel_launch(void* const* d_in, const int* in_sizes, int n_in,
                              void* d_out, int out_size) {
    const float* x    = (const float*)d_in[0];
    const int*   esrc = (const int*)d_in[1];
    const int*   edst = (const int*)d_in[2];
    const float* ev   = (const float*)d_in[3];
    const float* W1   = (const float*)d_in[4];
    const float* b1   = (const float*)d_in[5];
    const float* W2   = (const float*)d_in[6];
    const float* b2   = (const float*)d_in[7];
    float* out = (float*)d_out;

    int E = in_sizes[1];
    int N = in_sizes[0] / 256;

    int eq = (E + 3) / 4;
    int nq = (N + 3) / 4;
    int nb = (N + SCAN_BLK - 1) / SCAN_BLK;

    // CSR build (gemm1 slotted at launch index 3 so ncu -s5 profiles it)
    zero_off_kernel<<<(nq + 255) / 256, 256>>>(N);            // 0
    hist_kernel<<<(eq + 255) / 256, 256>>>(edst, E);          // 1
    scan_a_kernel<<<nb, SCAN_BLK>>>(N);                       // 2
    gemm1_kernel<<<(N + 127) / 128, 128>>>(x, W1, N);         // 3 <- profiled
    scan_b_kernel<<<1, 1024>>>(nb);                           // 4
    scan_c_kernel<<<nb, SCAN_BLK>>>(N);                       // 5
    scatter_kernel<<<(eq + 255) / 256, 256>>>(esrc, edst, ev, E);  // 6

    // Layer 1 + gemm2 fused
    spmm1_gemm2_kernel<<<(N * 16 + 255) / 256, 256>>>(b1, W2, N);  // 7

    // Layer 2 + log_softmax
    spmm2_kernel<<<(N * 4 + 255) / 256, 256>>>(b2, out, N);        // 8
}

// round 5
// speedup vs baseline: 1.6169x; 1.0192x over previous
#include <cuda_runtime.h>
#include <cuda_bf16.h>
#include <math.h>
#include <stdint.h>
#include <mma.h>

using namespace nvcuda;

// GCN: out = log_softmax( spmm(adj, relu(spmm(adj, x@W1)+b1) @ W2) + b2 )
// R5: tcgen05 unavailable (harness PTX target = compute_103, feature-gated).
//     GEMM1 on legacy mma.sync tf32 via wmma (sm_80-baseline PTX, works on
//     compute_103). Rest identical to the 217us R3 kernel.

#define MAXN 100000
#define MAXE 1600000
#define SCAN_BLK 256

__device__ int   g_off[MAXN];            // counts -> starts -> ends
__device__ int   g_bsum[1024];           // block sums for scan
__device__ int2  g_csr[MAXE];            // (src, val bits)
__device__ float g_support1[(size_t)MAXN * 64];
__device__ float g_support2[(size_t)MAXN * 16];

static __device__ __forceinline__ float cvt_tf32f(float f) {
    uint32_t r;
    asm("cvt.rna.tf32.f32 %0, %1;" : "=r"(r) : "f"(f));
    return __uint_as_float(r);
}

// ---------------------------------------------------------------- CSR build
__global__ void zero_off_kernel(int N) {
    int i = (blockIdx.x * blockDim.x + threadIdx.x) * 4;
    if (i + 4 <= N) {
        *(int4*)&g_off[i] = make_int4(0, 0, 0, 0);
    } else {
        for (int j = i; j < N; j++) g_off[j] = 0;
    }
}

__global__ void hist_kernel(const int* __restrict__ dst, int E) {
    int i = (blockIdx.x * blockDim.x + threadIdx.x) * 4;
    if (i + 4 <= E) {
        int4 d = *(const int4*)(dst + i);
        atomicAdd(&g_off[d.x], 1);
        atomicAdd(&g_off[d.y], 1);
        atomicAdd(&g_off[d.z], 1);
        atomicAdd(&g_off[d.w], 1);
    } else {
        for (int j = i; j < E; j++) atomicAdd(&g_off[dst[j]], 1);
    }
}

__global__ void scan_a_kernel(int N) {
    __shared__ int ws[8];
    int i = blockIdx.x * SCAN_BLK + threadIdx.x;
    int v = (i < N) ? g_off[i] : 0;
    int lane = threadIdx.x & 31, w = threadIdx.x >> 5;
    int s = v;
    #pragma unroll
    for (int d = 16; d > 0; d >>= 1) s += __shfl_xor_sync(0xFFFFFFFFu, s, d);
    if (lane == 0) ws[w] = s;
    __syncthreads();
    if (threadIdx.x == 0) {
        int t = 0;
        #pragma unroll
        for (int k = 0; k < 8; k++) t += ws[k];
        g_bsum[blockIdx.x] = t;
    }
}

__global__ void scan_b_kernel(int nb) {
    __shared__ int wsum[32];
    int t = threadIdx.x;  // 1024
    int v = (t < nb) ? g_bsum[t] : 0;
    int lane = t & 31, w = t >> 5;
    int incl = v;
    #pragma unroll
    for (int d = 1; d < 32; d <<= 1) {
        int n = __shfl_up_sync(0xFFFFFFFFu, incl, d);
        if (lane >= d) incl += n;
    }
    if (lane == 31) wsum[w] = incl;
    __syncthreads();
    if (w == 0) {
        int s = wsum[lane];
        #pragma unroll
        for (int d = 1; d < 32; d <<= 1) {
            int n = __shfl_up_sync(0xFFFFFFFFu, s, d);
            if (lane >= d) s += n;
        }
        wsum[lane] = s;
    }
    __syncthreads();
    int excl = incl - v + (w ? wsum[w - 1] : 0);
    if (t < nb) g_bsum[t] = excl;
}

__global__ void scan_c_kernel(int N) {
    __shared__ int ws[8];
    int i = blockIdx.x * SCAN_BLK + threadIdx.x;
    int v = (i < N) ? g_off[i] : 0;
    int lane = threadIdx.x & 31, w = threadIdx.x >> 5;
    int incl = v;
    #pragma unroll
    for (int d = 1; d < 32; d <<= 1) {
        int n = __shfl_up_sync(0xFFFFFFFFu, incl, d);
        if (lane >= d) incl += n;
    }
    if (lane == 31) ws[w] = incl;
    __syncthreads();
    if (w == 0 && lane < 8) {
        int s = ws[lane];
        #pragma unroll
        for (int d = 1; d < 8; d <<= 1) {
            int n = __shfl_up_sync(0x000000FFu, s, d);
            if (lane >= d) s += n;
        }
        ws[lane] = s;
    }
    __syncthreads();
    int excl = incl - v + (w ? ws[w - 1] : 0);
    if (i < N) g_off[i] = g_bsum[blockIdx.x] + excl;
}

__global__ void scatter_kernel(const int* __restrict__ src,
                               const int* __restrict__ dst,
                               const float* __restrict__ val, int E) {
    int i = (blockIdx.x * blockDim.x + threadIdx.x) * 4;
    if (i + 4 <= E) {
        int4   s = *(const int4*)(src + i);
        int4   d = *(const int4*)(dst + i);
        float4 v = *(const float4*)(val + i);
        int p0 = atomicAdd(&g_off[d.x], 1);
        int p1 = atomicAdd(&g_off[d.y], 1);
        int p2 = atomicAdd(&g_off[d.z], 1);
        int p3 = atomicAdd(&g_off[d.w], 1);
        g_csr[p0] = make_int2(s.x, __float_as_int(v.x));
        g_csr[p1] = make_int2(s.y, __float_as_int(v.y));
        g_csr[p2] = make_int2(s.z, __float_as_int(v.z));
        g_csr[p3] = make_int2(s.w, __float_as_int(v.w));
    } else {
        for (int j = i; j < E; j++) {
            int p = atomicAdd(&g_off[dst[j]], 1);
            g_csr[p] = make_int2(src[j], __float_as_int(val[j]));
        }
    }
}

// ---------------------------------------------------------------- GEMM1 (wmma tf32)
// support1[N,64] = x[N,256] @ W1[256,64].
// CTA: 128x64 output, 256 threads (8 warps). Warp w computes rows
// [w*16, w*16+16) x all 64 cols (4 wmma 16x16x8 fragments).
// K in 8 chunks of 32 staged through smem (tf32-converted).
__global__ void __launch_bounds__(256)
gemm1_wmma_kernel(const float* __restrict__ x, const float* __restrict__ W1,
                  int N) {
    __shared__ float smem[8192];       // 32KB: As(128x32)+Bs(32x64) / out(128x64)
    float* As = smem;                  // [128][32]
    float* Bs = smem + 4096;           // [32][64]

    int tid = threadIdx.x, wid = tid >> 5;
    int m0 = blockIdx.x * 128;

    wmma::fragment<wmma::accumulator, 16, 16, 8, float> acc[4];
    #pragma unroll
    for (int nt = 0; nt < 4; nt++) wmma::fill_fragment(acc[nt], 0.0f);

    for (int k0 = 0; k0 < 256; k0 += 32) {
        // A: 128x32 floats, 1024 float4, 4 per thread
        #pragma unroll
        for (int j = 0; j < 4; j++) {
            int i = tid + (j << 8);            // 0..1023 float4 index
            int row = i >> 3;
            int c4 = (i & 7) << 2;
            int gr = m0 + row;
            float4 v = make_float4(0.f, 0.f, 0.f, 0.f);
            if (gr < N)
                v = *(const float4*)(x + (size_t)gr * 256 + k0 + c4);
            float4 t = make_float4(cvt_tf32f(v.x), cvt_tf32f(v.y),
                                   cvt_tf32f(v.z), cvt_tf32f(v.w));
            *(float4*)&As[row * 32 + c4] = t;
        }
        // B: rows k0..k0+31 of W1 (already [k][n], contiguous 2048 floats)
        #pragma unroll
        for (int j = 0; j < 2; j++) {
            int i = tid + (j << 8);            // 0..511 float4 index
            float4 v = *(const float4*)(W1 + (size_t)k0 * 64 + i * 4);
            float4 t = make_float4(cvt_tf32f(v.x), cvt_tf32f(v.y),
                                   cvt_tf32f(v.z), cvt_tf32f(v.w));
            *(float4*)&Bs[i * 4] = t;
        }
        __syncthreads();

        #pragma unroll
        for (int kk = 0; kk < 4; kk++) {
            wmma::fragment<wmma::matrix_a, 16, 16, 8, wmma::precision::tf32,
                           wmma::row_major> a_frag;
            wmma::load_matrix_sync(a_frag, &As[(wid * 16) * 32 + kk * 8], 32);
            #pragma unroll
            for (int nt = 0; nt < 4; nt++) {
                wmma::fragment<wmma::matrix_b, 16, 16, 8, wmma::precision::tf32,
                               wmma::row_major> b_frag;
                wmma::load_matrix_sync(b_frag, &Bs[(kk * 8) * 64 + nt * 16], 64);
                wmma::mma_sync(acc[nt], a_frag, b_frag, acc[nt]);
            }
        }
        __syncthreads();
    }

    // Epilogue through smem (handles N boundary), reuse smem as 128x64.
    #pragma unroll
    for (int nt = 0; nt < 4; nt++)
        wmma::store_matrix_sync(&smem[(wid * 16) * 64 + nt * 16], acc[nt], 64,
                                wmma::mem_row_major);
    __syncthreads();

    // copy out: 8192 floats = 2048 float4, 8 per thread
    #pragma unroll
    for (int j = 0; j < 8; j++) {
        int i = tid + (j << 8);        // float4 index
        int row = i >> 4;
        int c4 = (i & 15) << 2;
        int gr = m0 + row;
        if (gr < N)
            *(float4*)&g_support1[(size_t)gr * 64 + c4] =
                *(const float4*)&smem[row * 64 + c4];
    }
}

// ---------------------------------------- spMM1 + (relu,b1) + GEMM2 fused
__global__ void spmm1_gemm2_kernel(const float* __restrict__ b1,
                                   const float* __restrict__ W2, int N) {
    __shared__ float w2t[16][68];   // transposed W2, padded
    int tid = threadIdx.x;          // 256
    for (int i = tid; i < 64 * 16; i += 256) {
        int k = i >> 4, j = i & 15;
        w2t[j][k] = W2[i];
    }
    __syncthreads();

    int t = blockIdx.x * 256 + tid;
    int node = t >> 4;
    int c = (t & 15) << 2;
    bool valid = (node < N);

    float4 acc = make_float4(0.f, 0.f, 0.f, 0.f);
    if (valid) {
        int start = node ? g_off[node - 1] : 0;
        int end = g_off[node];
        int e = start;
        for (; e + 4 <= end; e += 4) {
            int2 e0 = g_csr[e], e1 = g_csr[e + 1], e2 = g_csr[e + 2], e3 = g_csr[e + 3];
            float4 v0 = *(const float4*)&g_support1[(size_t)e0.x * 64 + c];
            float4 v1 = *(const float4*)&g_support1[(size_t)e1.x * 64 + c];
            float4 v2 = *(const float4*)&g_support1[(size_t)e2.x * 64 + c];
            float4 v3 = *(const float4*)&g_support1[(size_t)e3.x * 64 + c];
            float w0 = __int_as_float(e0.y), w1 = __int_as_float(e1.y);
            float w2 = __int_as_float(e2.y), w3 = __int_as_float(e3.y);
            acc.x = fmaf(w0, v0.x, acc.x); acc.y = fmaf(w0, v0.y, acc.y);
            acc.z = fmaf(w0, v0.z, acc.z); acc.w = fmaf(w0, v0.w, acc.w);
            acc.x = fmaf(w1, v1.x, acc.x); acc.y = fmaf(w1, v1.y, acc.y);
            acc.z = fmaf(w1, v1.z, acc.z); acc.w = fmaf(w1, v1.w, acc.w);
            acc.x = fmaf(w2, v2.x, acc.x); acc.y = fmaf(w2, v2.y, acc.y);
            acc.z = fmaf(w2, v2.z, acc.z); acc.w = fmaf(w2, v2.w, acc.w);
            acc.x = fmaf(w3, v3.x, acc.x); acc.y = fmaf(w3, v3.y, acc.y);
            acc.z = fmaf(w3, v3.z, acc.z); acc.w = fmaf(w3, v3.w, acc.w);
        }
        for (; e < end; e++) {
            int2 ed = g_csr[e];
            float w = __int_as_float(ed.y);
            float4 v = *(const float4*)&g_support1[(size_t)ed.x * 64 + c];
            acc.x = fmaf(w, v.x, acc.x); acc.y = fmaf(w, v.y, acc.y);
            acc.z = fmaf(w, v.z, acc.z); acc.w = fmaf(w, v.w, acc.w);
        }
        float4 bb = *(const float4*)&b1[c];
        acc.x = fmaxf(acc.x + bb.x, 0.f);
        acc.y = fmaxf(acc.y + bb.y, 0.f);
        acc.z = fmaxf(acc.z + bb.z, 0.f);
        acc.w = fmaxf(acc.w + bb.w, 0.f);
    }

    float part[16];
    #pragma unroll
    for (int j = 0; j < 16; j++) {
        float s = acc.x * w2t[j][c];
        s = fmaf(acc.y, w2t[j][c + 1], s);
        s = fmaf(acc.z, w2t[j][c + 2], s);
        s = fmaf(acc.w, w2t[j][c + 3], s);
        part[j] = s;
    }
    #pragma unroll
    for (int d = 1; d < 16; d <<= 1) {
        #pragma unroll
        for (int j = 0; j < 16; j++)
            part[j] += __shfl_xor_sync(0xFFFFFFFFu, part[j], d);
    }
    int sub = t & 15;
    if (valid && sub < 4) {
        *(float4*)&g_support2[(size_t)node * 16 + sub * 4] =
            make_float4(part[sub * 4], part[sub * 4 + 1],
                        part[sub * 4 + 2], part[sub * 4 + 3]);
    }
}

// ------------------------------------------------ spMM2 + log_softmax fused
__global__ void spmm2_kernel(const float* __restrict__ b2,
                             float* __restrict__ out, int N) {
    int t = blockIdx.x * blockDim.x + threadIdx.x;
    int node = t >> 2;
    int q = (t & 3) << 2;

    float4 acc = make_float4(0.f, 0.f, 0.f, 0.f);
    if (node < N) {
        int start = node ? g_off[node - 1] : 0;
        int end = g_off[node];
        int e = start;
        for (; e + 4 <= end; e += 4) {
            int2 e0 = g_csr[e], e1 = g_csr[e + 1], e2 = g_csr[e + 2], e3 = g_csr[e + 3];
            float4 v0 = *(const float4*)&g_support2[(size_t)e0.x * 16 + q];
            float4 v1 = *(const float4*)&g_support2[(size_t)e1.x * 16 + q];
            float4 v2 = *(const float4*)&g_support2[(size_t)e2.x * 16 + q];
            float4 v3 = *(const float4*)&g_support2[(size_t)e3.x * 16 + q];
            float w0 = __int_as_float(e0.y), w1 = __int_as_float(e1.y);
            float w2 = __int_as_float(e2.y), w3 = __int_as_float(e3.y);
            acc.x = fmaf(w0, v0.x, acc.x); acc.y = fmaf(w0, v0.y, acc.y);
            acc.z = fmaf(w0, v0.z, acc.z); acc.w = fmaf(w0, v0.w, acc.w);
            acc.x = fmaf(w1, v1.x, acc.x); acc.y = fmaf(w1, v1.y, acc.y);
            acc.z = fmaf(w1, v1.z, acc.z); acc.w = fmaf(w1, v1.w, acc.w);
            acc.x = fmaf(w2, v2.x, acc.x); acc.y = fmaf(w2, v2.y, acc.y);
            acc.z = fmaf(w2, v2.z, acc.z); acc.w = fmaf(w2, v2.w, acc.w);
            acc.x = fmaf(w3, v3.x, acc.x); acc.y = fmaf(w3, v3.y, acc.y);
            acc.z = fmaf(w3, v3.z, acc.z); acc.w = fmaf(w3, v3.w, acc.w);
        }
        for (; e < end; e++) {
            int2 ed = g_csr[e];
            float w = __int_as_float(ed.y);
            float4 v = *(const float4*)&g_support2[(size_t)ed.x * 16 + q];
            acc.x = fmaf(w, v.x, acc.x); acc.y = fmaf(w, v.y, acc.y);
            acc.z = fmaf(w, v.z, acc.z); acc.w = fmaf(w, v.w, acc.w);
        }
        float4 bb = *(const float4*)&b2[q];
        acc.x += bb.x; acc.y += bb.y; acc.z += bb.z; acc.w += bb.w;
    }

    float m = fmaxf(fmaxf(acc.x, acc.y), fmaxf(acc.z, acc.w));
    m = fmaxf(m, __shfl_xor_sync(0xFFFFFFFFu, m, 1));
    m = fmaxf(m, __shfl_xor_sync(0xFFFFFFFFu, m, 2));
    float s = expf(acc.x - m) + expf(acc.y - m) + expf(acc.z - m) + expf(acc.w - m);
    s += __shfl_xor_sync(0xFFFFFFFFu, s, 1);
    s += __shfl_xor_sync(0xFFFFFFFFu, s, 2);
    float lse = m + logf(s);

    if (node < N) {
        *(float4*)&out[(size_t)node * 16 + q] =
            make_float4(acc.x - lse, acc.y - lse, acc.z - lse, acc.w - lse);
    }
}

// ---------------------------------------------------------------- launch
extern "C" void kernel_launch(void* const* d_in, const int* in_sizes, int n_in,
                              void* d_out, int out_size) {
    const float* x    = (const float*)d_in[0];
    const int*   esrc = (const int*)d_in[1];
    const int*   edst = (const int*)d_in[2];
    const float* ev   = (const float*)d_in[3];
    const float* W1   = (const float*)d_in[4];
    const float* b1   = (const float*)d_in[5];
    const float* W2   = (const float*)d_in[6];
    const float* b2   = (const float*)d_in[7];
    float* out = (float*)d_out;

    int E = in_sizes[1];
    int N = in_sizes[0] / 256;

    int eq = (E + 3) / 4;
    int nq = (N + 3) / 4;
    int nb = (N + SCAN_BLK - 1) / SCAN_BLK;

    // CSR build (gemm1 slotted at launch index 3 so ncu profiles it)
    zero_off_kernel<<<(nq + 255) / 256, 256>>>(N);                 // 0
    hist_kernel<<<(eq + 255) / 256, 256>>>(edst, E);               // 1
    scan_a_kernel<<<nb, SCAN_BLK>>>(N);                            // 2
    gemm1_wmma_kernel<<<(N + 127) / 128, 256>>>(x, W1, N);         // 3 <- profiled
    scan_b_kernel<<<1, 1024>>>(nb);                                // 4
    scan_c_kernel<<<nb, SCAN_BLK>>>(N);                            // 5
    scatter_kernel<<<(eq + 255) / 256, 256>>>(esrc, edst, ev, E);  // 6

    // Layer 1 + gemm2 fused
    spmm1_gemm2_kernel<<<(N * 16 + 255) / 256, 256>>>(b1, W2, N);  // 7

    // Layer 2 + log_softmax
    spmm2_kernel<<<(N * 4 + 255) / 256, 256>>>(b2, out, N);        // 8
}

// round 6
// speedup vs baseline: 1.8102x; 1.1195x over previous
#include <cuda_runtime.h>
#include <cuda_bf16.h>
#include <math.h>
#include <stdint.h>
#include <mma.h>

using namespace nvcuda;

// GCN: out = log_softmax( spmm(adj, relu(spmm(adj, x@W1)+b1) @ W2) + b2 )
// R6: gemm1 wmma retuned: 4 warps/CTA, 32 rows/warp (acc[2][4]) to halve
//     redundant B-fragment smem traffic, direct store_matrix_sync epilogue
//     into a row-padded support1 buffer. Rest identical to R5.

#define MAXN 100000
#define MAXE 1600000
#define SCAN_BLK 256

__device__ int   g_off[MAXN];            // counts -> starts -> ends
__device__ int   g_bsum[1024];           // block sums for scan
__device__ int2  g_csr[MAXE];            // (src, val bits)
__device__ float g_support1[(size_t)(MAXN + 128) * 64];  // row-padded for wmma store
__device__ float g_support2[(size_t)MAXN * 16];

static __device__ __forceinline__ float cvt_tf32f(float f) {
    uint32_t r;
    asm("cvt.rna.tf32.f32 %0, %1;" : "=r"(r) : "f"(f));
    return __uint_as_float(r);
}

// ---------------------------------------------------------------- CSR build
__global__ void zero_off_kernel(int N) {
    int i = (blockIdx.x * blockDim.x + threadIdx.x) * 4;
    if (i + 4 <= N) {
        *(int4*)&g_off[i] = make_int4(0, 0, 0, 0);
    } else {
        for (int j = i; j < N; j++) g_off[j] = 0;
    }
}

__global__ void hist_kernel(const int* __restrict__ dst, int E) {
    int i = (blockIdx.x * blockDim.x + threadIdx.x) * 4;
    if (i + 4 <= E) {
        int4 d = *(const int4*)(dst + i);
        atomicAdd(&g_off[d.x], 1);
        atomicAdd(&g_off[d.y], 1);
        atomicAdd(&g_off[d.z], 1);
        atomicAdd(&g_off[d.w], 1);
    } else {
        for (int j = i; j < E; j++) atomicAdd(&g_off[dst[j]], 1);
    }
}

__global__ void scan_a_kernel(int N) {
    __shared__ int ws[8];
    int i = blockIdx.x * SCAN_BLK + threadIdx.x;
    int v = (i < N) ? g_off[i] : 0;
    int lane = threadIdx.x & 31, w = threadIdx.x >> 5;
    int s = v;
    #pragma unroll
    for (int d = 16; d > 0; d >>= 1) s += __shfl_xor_sync(0xFFFFFFFFu, s, d);
    if (lane == 0) ws[w] = s;
    __syncthreads();
    if (threadIdx.x == 0) {
        int t = 0;
        #pragma unroll
        for (int k = 0; k < 8; k++) t += ws[k];
        g_bsum[blockIdx.x] = t;
    }
}

__global__ void scan_b_kernel(int nb) {
    __shared__ int wsum[32];
    int t = threadIdx.x;  // 1024
    int v = (t < nb) ? g_bsum[t] : 0;
    int lane = t & 31, w = t >> 5;
    int incl = v;
    #pragma unroll
    for (int d = 1; d < 32; d <<= 1) {
        int n = __shfl_up_sync(0xFFFFFFFFu, incl, d);
        if (lane >= d) incl += n;
    }
    if (lane == 31) wsum[w] = incl;
    __syncthreads();
    if (w == 0) {
        int s = wsum[lane];
        #pragma unroll
        for (int d = 1; d < 32; d <<= 1) {
            int n = __shfl_up_sync(0xFFFFFFFFu, s, d);
            if (lane >= d) s += n;
        }
        wsum[lane] = s;
    }
    __syncthreads();
    int excl = incl - v + (w ? wsum[w - 1] : 0);
    if (t < nb) g_bsum[t] = excl;
}

__global__ void scan_c_kernel(int N) {
    __shared__ int ws[8];
    int i = blockIdx.x * SCAN_BLK + threadIdx.x;
    int v = (i < N) ? g_off[i] : 0;
    int lane = threadIdx.x & 31, w = threadIdx.x >> 5;
    int incl = v;
    #pragma unroll
    for (int d = 1; d < 32; d <<= 1) {
        int n = __shfl_up_sync(0xFFFFFFFFu, incl, d);
        if (lane >= d) incl += n;
    }
    if (lane == 31) ws[w] = incl;
    __syncthreads();
    if (w == 0 && lane < 8) {
        int s = ws[lane];
        #pragma unroll
        for (int d = 1; d < 8; d <<= 1) {
            int n = __shfl_up_sync(0x000000FFu, s, d);
            if (lane >= d) s += n;
        }
        ws[lane] = s;
    }
    __syncthreads();
    int excl = incl - v + (w ? ws[w - 1] : 0);
    if (i < N) g_off[i] = g_bsum[blockIdx.x] + excl;
}

__global__ void scatter_kernel(const int* __restrict__ src,
                               const int* __restrict__ dst,
                               const float* __restrict__ val, int E) {
    int i = (blockIdx.x * blockDim.x + threadIdx.x) * 4;
    if (i + 4 <= E) {
        int4   s = *(const int4*)(src + i);
        int4   d = *(const int4*)(dst + i);
        float4 v = *(const float4*)(val + i);
        int p0 = atomicAdd(&g_off[d.x], 1);
        int p1 = atomicAdd(&g_off[d.y], 1);
        int p2 = atomicAdd(&g_off[d.z], 1);
        int p3 = atomicAdd(&g_off[d.w], 1);
        g_csr[p0] = make_int2(s.x, __float_as_int(v.x));
        g_csr[p1] = make_int2(s.y, __float_as_int(v.y));
        g_csr[p2] = make_int2(s.z, __float_as_int(v.z));
        g_csr[p3] = make_int2(s.w, __float_as_int(v.w));
    } else {
        for (int j = i; j < E; j++) {
            int p = atomicAdd(&g_off[dst[j]], 1);
            g_csr[p] = make_int2(src[j], __float_as_int(val[j]));
        }
    }
}

// ---------------------------------------------------------------- GEMM1 (wmma tf32)
// support1[N,64] = x[N,256] @ W1[256,64].
// CTA: 128 threads (4 warps), 128x64 output tile. Warp w: rows
// [w*32, w*32+32) -> acc[2][4] wmma 16x16x8 fragments. K: 8 chunks of 32.
// Epilogue stores fragments directly to the row-padded g_support1.
__global__ void __launch_bounds__(128)
gemm1_wmma_kernel(const float* __restrict__ x, const float* __restrict__ W1,
                  int N) {
    __shared__ float As[128 * 32];     // 16KB
    __shared__ float Bs[32 * 64];      // 8KB

    int tid = threadIdx.x, wid = tid >> 5;
    int m0 = blockIdx.x * 128;

    wmma::fragment<wmma::accumulator, 16, 16, 8, float> acc[2][4];
    #pragma unroll
    for (int i = 0; i < 2; i++)
        #pragma unroll
        for (int nt = 0; nt < 4; nt++) wmma::fill_fragment(acc[i][nt], 0.0f);

    for (int k0 = 0; k0 < 256; k0 += 32) {
        // A: 128x32 floats = 1024 float4, 8 per thread
        #pragma unroll
        for (int j = 0; j < 8; j++) {
            int i = tid + (j << 7);            // float4 index
            int row = i >> 3;
            int c4 = (i & 7) << 2;
            int gr = m0 + row;
            float4 v = make_float4(0.f, 0.f, 0.f, 0.f);
            if (gr < N)
                v = *(const float4*)(x + (size_t)gr * 256 + k0 + c4);
            float4 t = make_float4(cvt_tf32f(v.x), cvt_tf32f(v.y),
                                   cvt_tf32f(v.z), cvt_tf32f(v.w));
            *(float4*)&As[row * 32 + c4] = t;
        }
        // B: 32x64 floats = 512 float4, 4 per thread
        #pragma unroll
        for (int j = 0; j < 4; j++) {
            int i = tid + (j << 7);
            float4 v = *(const float4*)(W1 + (size_t)k0 * 64 + i * 4);
            float4 t = make_float4(cvt_tf32f(v.x), cvt_tf32f(v.y),
                                   cvt_tf32f(v.z), cvt_tf32f(v.w));
            *(float4*)&Bs[i * 4] = t;
        }
        __syncthreads();

        #pragma unroll
        for (int kk = 0; kk < 4; kk++) {
            wmma::fragment<wmma::matrix_a, 16, 16, 8, wmma::precision::tf32,
                           wmma::row_major> a0, a1;
            wmma::load_matrix_sync(a0, &As[(wid * 32) * 32 + kk * 8], 32);
            wmma::load_matrix_sync(a1, &As[(wid * 32 + 16) * 32 + kk * 8], 32);
            #pragma unroll
            for (int nt = 0; nt < 4; nt++) {
                wmma::fragment<wmma::matrix_b, 16, 16, 8, wmma::precision::tf32,
                               wmma::row_major> b_frag;
                wmma::load_matrix_sync(b_frag, &Bs[(kk * 8) * 64 + nt * 16], 64);
                wmma::mma_sync(acc[0][nt], a0, b_frag, acc[0][nt]);
                wmma::mma_sync(acc[1][nt], a1, b_frag, acc[1][nt]);
            }
        }
        __syncthreads();
    }

    // Direct global store; rows beyond N land in the padded tail (harmless).
    #pragma unroll
    for (int i = 0; i < 2; i++) {
        int r0 = m0 + wid * 32 + i * 16;
        #pragma unroll
        for (int nt = 0; nt < 4; nt++)
            wmma::store_matrix_sync(&g_support1[(size_t)r0 * 64 + nt * 16],
                                    acc[i][nt], 64, wmma::mem_row_major);
    }
}

// ---------------------------------------- spMM1 + (relu,b1) + GEMM2 fused
__global__ void spmm1_gemm2_kernel(const float* __restrict__ b1,
                                   const float* __restrict__ W2, int N) {
    __shared__ float w2t[16][68];   // transposed W2, padded
    int tid = threadIdx.x;          // 256
    for (int i = tid; i < 64 * 16; i += 256) {
        int k = i >> 4, j = i & 15;
        w2t[j][k] = W2[i];
    }
    __syncthreads();

    int t = blockIdx.x * 256 + tid;
    int node = t >> 4;
    int c = (t & 15) << 2;
    bool valid = (node < N);

    float4 acc = make_float4(0.f, 0.f, 0.f, 0.f);
    if (valid) {
        int start = node ? g_off[node - 1] : 0;
        int end = g_off[node];
        int e = start;
        for (; e + 4 <= end; e += 4) {
            int2 e0 = g_csr[e], e1 = g_csr[e + 1], e2 = g_csr[e + 2], e3 = g_csr[e + 3];
            float4 v0 = *(const float4*)&g_support1[(size_t)e0.x * 64 + c];
            float4 v1 = *(const float4*)&g_support1[(size_t)e1.x * 64 + c];
            float4 v2 = *(const float4*)&g_support1[(size_t)e2.x * 64 + c];
            float4 v3 = *(const float4*)&g_support1[(size_t)e3.x * 64 + c];
            float w0 = __int_as_float(e0.y), w1 = __int_as_float(e1.y);
            float w2 = __int_as_float(e2.y), w3 = __int_as_float(e3.y);
            acc.x = fmaf(w0, v0.x, acc.x); acc.y = fmaf(w0, v0.y, acc.y);
            acc.z = fmaf(w0, v0.z, acc.z); acc.w = fmaf(w0, v0.w, acc.w);
            acc.x = fmaf(w1, v1.x, acc.x); acc.y = fmaf(w1, v1.y, acc.y);
            acc.z = fmaf(w1, v1.z, acc.z); acc.w = fmaf(w1, v1.w, acc.w);
            acc.x = fmaf(w2, v2.x, acc.x); acc.y = fmaf(w2, v2.y, acc.y);
            acc.z = fmaf(w2, v2.z, acc.z); acc.w = fmaf(w2, v2.w, acc.w);
            acc.x = fmaf(w3, v3.x, acc.x); acc.y = fmaf(w3, v3.y, acc.y);
            acc.z = fmaf(w3, v3.z, acc.z); acc.w = fmaf(w3, v3.w, acc.w);
        }
        for (; e < end; e++) {
            int2 ed = g_csr[e];
            float w = __int_as_float(ed.y);
            float4 v = *(const float4*)&g_support1[(size_t)ed.x * 64 + c];
            acc.x = fmaf(w, v.x, acc.x); acc.y = fmaf(w, v.y, acc.y);
            acc.z = fmaf(w, v.z, acc.z); acc.w = fmaf(w, v.w, acc.w);
        }
        float4 bb = *(const float4*)&b1[c];
        acc.x = fmaxf(acc.x + bb.x, 0.f);
        acc.y = fmaxf(acc.y + bb.y, 0.f);
        acc.z = fmaxf(acc.z + bb.z, 0.f);
        acc.w = fmaxf(acc.w + bb.w, 0.f);
    }

    float part[16];
    #pragma unroll
    for (int j = 0; j < 16; j++) {
        float s = acc.x * w2t[j][c];
        s = fmaf(acc.y, w2t[j][c + 1], s);
        s = fmaf(acc.z, w2t[j][c + 2], s);
        s = fmaf(acc.w, w2t[j][c + 3], s);
        part[j] = s;
    }
    #pragma unroll
    for (int d = 1; d < 16; d <<= 1) {
        #pragma unroll
        for (int j = 0; j < 16; j++)
            part[j] += __shfl_xor_sync(0xFFFFFFFFu, part[j], d);
    }
    int sub = t & 15;
    if (valid && sub < 4) {
        *(float4*)&g_support2[(size_t)node * 16 + sub * 4] =
            make_float4(part[sub * 4], part[sub * 4 + 1],
                        part[sub * 4 + 2], part[sub * 4 + 3]);
    }
}

// ------------------------------------------------ spMM2 + log_softmax fused
__global__ void spmm2_kernel(const float* __restrict__ b2,
                             float* __restrict__ out, int N) {
    int t = blockIdx.x * blockDim.x + threadIdx.x;
    int node = t >> 2;
    int q = (t & 3) << 2;

    float4 acc = make_float4(0.f, 0.f, 0.f, 0.f);
    if (node < N) {
        int start = node ? g_off[node - 1] : 0;
        int end = g_off[node];
        int e = start;
        for (; e + 4 <= end; e += 4) {
            int2 e0 = g_csr[e], e1 = g_csr[e + 1], e2 = g_csr[e + 2], e3 = g_csr[e + 3];
            float4 v0 = *(const float4*)&g_support2[(size_t)e0.x * 16 + q];
            float4 v1 = *(const float4*)&g_support2[(size_t)e1.x * 16 + q];
            float4 v2 = *(const float4*)&g_support2[(size_t)e2.x * 16 + q];
            float4 v3 = *(const float4*)&g_support2[(size_t)e3.x * 16 + q];
            float w0 = __int_as_float(e0.y), w1 = __int_as_float(e1.y);
            float w2 = __int_as_float(e2.y), w3 = __int_as_float(e3.y);
            acc.x = fmaf(w0, v0.x, acc.x); acc.y = fmaf(w0, v0.y, acc.y);
            acc.z = fmaf(w0, v0.z, acc.z); acc.w = fmaf(w0, v0.w, acc.w);
            acc.x = fmaf(w1, v1.x, acc.x); acc.y = fmaf(w1, v1.y, acc.y);
            acc.z = fmaf(w1, v1.z, acc.z); acc.w = fmaf(w1, v1.w, acc.w);
            acc.x = fmaf(w2, v2.x, acc.x); acc.y = fmaf(w2, v2.y, acc.y);
            acc.z = fmaf(w2, v2.z, acc.z); acc.w = fmaf(w2, v2.w, acc.w);
            acc.x = fmaf(w3, v3.x, acc.x); acc.y = fmaf(w3, v3.y, acc.y);
            acc.z = fmaf(w3, v3.z, acc.z); acc.w = fmaf(w3, v3.w, acc.w);
        }
        for (; e < end; e++) {
            int2 ed = g_csr[e];
            float w = __int_as_float(ed.y);
            float4 v = *(const float4*)&g_support2[(size_t)ed.x * 16 + q];
            acc.x = fmaf(w, v.x, acc.x); acc.y = fmaf(w, v.y, acc.y);
            acc.z = fmaf(w, v.z, acc.z); acc.w = fmaf(w, v.w, acc.w);
        }
        float4 bb = *(const float4*)&b2[q];
        acc.x += bb.x; acc.y += bb.y; acc.z += bb.z; acc.w += bb.w;
    }

    float m = fmaxf(fmaxf(acc.x, acc.y), fmaxf(acc.z, acc.w));
    m = fmaxf(m, __shfl_xor_sync(0xFFFFFFFFu, m, 1));
    m = fmaxf(m, __shfl_xor_sync(0xFFFFFFFFu, m, 2));
    float s = expf(acc.x - m) + expf(acc.y - m) + expf(acc.z - m) + expf(acc.w - m);
    s += __shfl_xor_sync(0xFFFFFFFFu, s, 1);
    s += __shfl_xor_sync(0xFFFFFFFFu, s, 2);
    float lse = m + logf(s);

    if (node < N) {
        *(float4*)&out[(size_t)node * 16 + q] =
            make_float4(acc.x - lse, acc.y - lse, acc.z - lse, acc.w - lse);
    }
}

// ---------------------------------------------------------------- launch
extern "C" void kernel_launch(void* const* d_in, const int* in_sizes, int n_in,
                              void* d_out, int out_size) {
    const float* x    = (const float*)d_in[0];
    const int*   esrc = (const int*)d_in[1];
    const int*   edst = (const int*)d_in[2];
    const float* ev   = (const float*)d_in[3];
    const float* W1   = (const float*)d_in[4];
    const float* b1   = (const float*)d_in[5];
    const float* W2   = (const float*)d_in[6];
    const float* b2   = (const float*)d_in[7];
    float* out = (float*)d_out;

    int E = in_sizes[1];
    int N = in_sizes[0] / 256;

    int eq = (E + 3) / 4;
    int nq = (N + 3) / 4;
    int nb = (N + SCAN_BLK - 1) / SCAN_BLK;

    // CSR build (gemm1 slotted at launch index 3 so ncu profiles it)
    zero_off_kernel<<<(nq + 255) / 256, 256>>>(N);                 // 0
    hist_kernel<<<(eq + 255) / 256, 256>>>(edst, E);               // 1
    scan_a_kernel<<<nb, SCAN_BLK>>>(N);                            // 2
    gemm1_wmma_kernel<<<(N + 127) / 128, 128>>>(x, W1, N);         // 3 <- profiled
    scan_b_kernel<<<1, 1024>>>(nb);                                // 4
    scan_c_kernel<<<nb, SCAN_BLK>>>(N);                            // 5
    scatter_kernel<<<(eq + 255) / 256, 256>>>(esrc, edst, ev, E);  // 6

    // Layer 1 + gemm2 fused
    spmm1_gemm2_kernel<<<(N * 16 + 255) / 256, 256>>>(b1, W2, N);  // 7

    // Layer 2 + log_softmax
    spmm2_kernel<<<(N * 4 + 255) / 256, 256>>>(b2, out, N);        // 8
}

// round 7
// speedup vs baseline: 1.9902x; 1.0994x over previous
#include <cuda_runtime.h>
#include <cuda_bf16.h>
#include <math.h>
#include <stdint.h>
#include <mma.h>

using namespace nvcuda;

// GCN: out = log_softmax( spmm(adj, relu(spmm(adj, x@W1)+b1) @ W2) + b2 )
// R7: gemm1 smem tiles padded (As ldm=36, Bs ldm=68) to kill the 4-way
//     bank conflicts on wmma fragment loads identified in R6's profile
//     (L1=69.6% with ldm=32/64: bank = col%32 for all rows). Rest = R6.

#define MAXN 100000
#define MAXE 1600000
#define SCAN_BLK 256
#define ALDM 36
#define BLDM 68

__device__ int   g_off[MAXN];            // counts -> starts -> ends
__device__ int   g_bsum[1024];           // block sums for scan
__device__ int2  g_csr[MAXE];            // (src, val bits)
__device__ float g_support1[(size_t)(MAXN + 128) * 64];  // row-padded for wmma store
__device__ float g_support2[(size_t)MAXN * 16];

static __device__ __forceinline__ float cvt_tf32f(float f) {
    uint32_t r;
    asm("cvt.rna.tf32.f32 %0, %1;" : "=r"(r) : "f"(f));
    return __uint_as_float(r);
}

// ---------------------------------------------------------------- CSR build
__global__ void zero_off_kernel(int N) {
    int i = (blockIdx.x * blockDim.x + threadIdx.x) * 4;
    if (i + 4 <= N) {
        *(int4*)&g_off[i] = make_int4(0, 0, 0, 0);
    } else {
        for (int j = i; j < N; j++) g_off[j] = 0;
    }
}

__global__ void hist_kernel(const int* __restrict__ dst, int E) {
    int i = (blockIdx.x * blockDim.x + threadIdx.x) * 4;
    if (i + 4 <= E) {
        int4 d = *(const int4*)(dst + i);
        atomicAdd(&g_off[d.x], 1);
        atomicAdd(&g_off[d.y], 1);
        atomicAdd(&g_off[d.z], 1);
        atomicAdd(&g_off[d.w], 1);
    } else {
        for (int j = i; j < E; j++) atomicAdd(&g_off[dst[j]], 1);
    }
}

__global__ void scan_a_kernel(int N) {
    __shared__ int ws[8];
    int i = blockIdx.x * SCAN_BLK + threadIdx.x;
    int v = (i < N) ? g_off[i] : 0;
    int lane = threadIdx.x & 31, w = threadIdx.x >> 5;
    int s = v;
    #pragma unroll
    for (int d = 16; d > 0; d >>= 1) s += __shfl_xor_sync(0xFFFFFFFFu, s, d);
    if (lane == 0) ws[w] = s;
    __syncthreads();
    if (threadIdx.x == 0) {
        int t = 0;
        #pragma unroll
        for (int k = 0; k < 8; k++) t += ws[k];
        g_bsum[blockIdx.x] = t;
    }
}

__global__ void scan_b_kernel(int nb) {
    __shared__ int wsum[32];
    int t = threadIdx.x;  // 1024
    int v = (t < nb) ? g_bsum[t] : 0;
    int lane = t & 31, w = t >> 5;
    int incl = v;
    #pragma unroll
    for (int d = 1; d < 32; d <<= 1) {
        int n = __shfl_up_sync(0xFFFFFFFFu, incl, d);
        if (lane >= d) incl += n;
    }
    if (lane == 31) wsum[w] = incl;
    __syncthreads();
    if (w == 0) {
        int s = wsum[lane];
        #pragma unroll
        for (int d = 1; d < 32; d <<= 1) {
            int n = __shfl_up_sync(0xFFFFFFFFu, s, d);
            if (lane >= d) s += n;
        }
        wsum[lane] = s;
    }
    __syncthreads();
    int excl = incl - v + (w ? wsum[w - 1] : 0);
    if (t < nb) g_bsum[t] = excl;
}

__global__ void scan_c_kernel(int N) {
    __shared__ int ws[8];
    int i = blockIdx.x * SCAN_BLK + threadIdx.x;
    int v = (i < N) ? g_off[i] : 0;
    int lane = threadIdx.x & 31, w = threadIdx.x >> 5;
    int incl = v;
    #pragma unroll
    for (int d = 1; d < 32; d <<= 1) {
        int n = __shfl_up_sync(0xFFFFFFFFu, incl, d);
        if (lane >= d) incl += n;
    }
    if (lane == 31) ws[w] = incl;
    __syncthreads();
    if (w == 0 && lane < 8) {
        int s = ws[lane];
        #pragma unroll
        for (int d = 1; d < 8; d <<= 1) {
            int n = __shfl_up_sync(0x000000FFu, s, d);
            if (lane >= d) s += n;
        }
        ws[lane] = s;
    }
    __syncthreads();
    int excl = incl - v + (w ? ws[w - 1] : 0);
    if (i < N) g_off[i] = g_bsum[blockIdx.x] + excl;
}

__global__ void scatter_kernel(const int* __restrict__ src,
                               const int* __restrict__ dst,
                               const float* __restrict__ val, int E) {
    int i = (blockIdx.x * blockDim.x + threadIdx.x) * 4;
    if (i + 4 <= E) {
        int4   s = *(const int4*)(src + i);
        int4   d = *(const int4*)(dst + i);
        float4 v = *(const float4*)(val + i);
        int p0 = atomicAdd(&g_off[d.x], 1);
        int p1 = atomicAdd(&g_off[d.y], 1);
        int p2 = atomicAdd(&g_off[d.z], 1);
        int p3 = atomicAdd(&g_off[d.w], 1);
        g_csr[p0] = make_int2(s.x, __float_as_int(v.x));
        g_csr[p1] = make_int2(s.y, __float_as_int(v.y));
        g_csr[p2] = make_int2(s.z, __float_as_int(v.z));
        g_csr[p3] = make_int2(s.w, __float_as_int(v.w));
    } else {
        for (int j = i; j < E; j++) {
            int p = atomicAdd(&g_off[dst[j]], 1);
            g_csr[p] = make_int2(src[j], __float_as_int(val[j]));
        }
    }
}

// ---------------------------------------------------------------- GEMM1 (wmma tf32)
// support1[N,64] = x[N,256] @ W1[256,64].
// CTA: 128 threads (4 warps), 128x64 tile. Warp w: rows [w*32, w*32+32),
// acc[2][4]. K: 8 chunks of 32. Padded smem strides (36/68) for
// conflict-free fragment loads. Direct wmma global store epilogue.
__global__ void __launch_bounds__(128, 3)
gemm1_wmma_kernel(const float* __restrict__ x, const float* __restrict__ W1,
                  int N) {
    __shared__ float As[128 * ALDM];   // 18KB
    __shared__ float Bs[32 * BLDM];    // 8.5KB

    int tid = threadIdx.x, wid = tid >> 5;
    int m0 = blockIdx.x * 128;

    wmma::fragment<wmma::accumulator, 16, 16, 8, float> acc[2][4];
    #pragma unroll
    for (int i = 0; i < 2; i++)
        #pragma unroll
        for (int nt = 0; nt < 4; nt++) wmma::fill_fragment(acc[i][nt], 0.0f);

    for (int k0 = 0; k0 < 256; k0 += 32) {
        // A: 128 rows x 32 cols, 1024 float4 slots, 8 per thread
        #pragma unroll
        for (int j = 0; j < 8; j++) {
            int i = tid + (j << 7);            // float4 index
            int row = i >> 3;
            int c4 = (i & 7) << 2;
            int gr = m0 + row;
            float4 v = make_float4(0.f, 0.f, 0.f, 0.f);
            if (gr < N)
                v = *(const float4*)(x + (size_t)gr * 256 + k0 + c4);
            float4 t = make_float4(cvt_tf32f(v.x), cvt_tf32f(v.y),
                                   cvt_tf32f(v.z), cvt_tf32f(v.w));
            *(float4*)&As[row * ALDM + c4] = t;
        }
        // B: 32 rows x 64 cols, 512 float4 slots, 4 per thread
        #pragma unroll
        for (int j = 0; j < 4; j++) {
            int i = tid + (j << 7);
            int row = i >> 4;
            int c4 = (i & 15) << 2;
            float4 v = *(const float4*)(W1 + (size_t)(k0 + row) * 64 + c4);
            float4 t = make_float4(cvt_tf32f(v.x), cvt_tf32f(v.y),
                                   cvt_tf32f(v.z), cvt_tf32f(v.w));
            *(float4*)&Bs[row * BLDM + c4] = t;
        }
        __syncthreads();

        #pragma unroll
        for (int kk = 0; kk < 4; kk++) {
            wmma::fragment<wmma::matrix_a, 16, 16, 8, wmma::precision::tf32,
                           wmma::row_major> a0, a1;
            wmma::load_matrix_sync(a0, &As[(wid * 32) * ALDM + kk * 8], ALDM);
            wmma::load_matrix_sync(a1, &As[(wid * 32 + 16) * ALDM + kk * 8], ALDM);
            #pragma unroll
            for (int nt = 0; nt < 4; nt++) {
                wmma::fragment<wmma::matrix_b, 16, 16, 8, wmma::precision::tf32,
                               wmma::row_major> b_frag;
                wmma::load_matrix_sync(b_frag, &Bs[(kk * 8) * BLDM + nt * 16], BLDM);
                wmma::mma_sync(acc[0][nt], a0, b_frag, acc[0][nt]);
                wmma::mma_sync(acc[1][nt], a1, b_frag, acc[1][nt]);
            }
        }
        __syncthreads();
    }

    // Direct global store; rows beyond N land in the padded tail (harmless).
    #pragma unroll
    for (int i = 0; i < 2; i++) {
        int r0 = m0 + wid * 32 + i * 16;
        #pragma unroll
        for (int nt = 0; nt < 4; nt++)
            wmma::store_matrix_sync(&g_support1[(size_t)r0 * 64 + nt * 16],
                                    acc[i][nt], 64, wmma::mem_row_major);
    }
}

// ---------------------------------------- spMM1 + (relu,b1) + GEMM2 fused
__global__ void spmm1_gemm2_kernel(const float* __restrict__ b1,
                                   const float* __restrict__ W2, int N) {
    __shared__ float w2t[16][68];   // transposed W2, padded
    int tid = threadIdx.x;          // 256
    for (int i = tid; i < 64 * 16; i += 256) {
        int k = i >> 4, j = i & 15;
        w2t[j][k] = W2[i];
    }
    __syncthreads();

    int t = blockIdx.x * 256 + tid;
    int node = t >> 4;
    int c = (t & 15) << 2;
    bool valid = (node < N);

    float4 acc = make_float4(0.f, 0.f, 0.f, 0.f);
    if (valid) {
        int start = node ? g_off[node - 1] : 0;
        int end = g_off[node];
        int e = start;
        for (; e + 4 <= end; e += 4) {
            int2 e0 = g_csr[e], e1 = g_csr[e + 1], e2 = g_csr[e + 2], e3 = g_csr[e + 3];
            float4 v0 = *(const float4*)&g_support1[(size_t)e0.x * 64 + c];
            float4 v1 = *(const float4*)&g_support1[(size_t)e1.x * 64 + c];
            float4 v2 = *(const float4*)&g_support1[(size_t)e2.x * 64 + c];
            float4 v3 = *(const float4*)&g_support1[(size_t)e3.x * 64 + c];
            float w0 = __int_as_float(e0.y), w1 = __int_as_float(e1.y);
            float w2 = __int_as_float(e2.y), w3 = __int_as_float(e3.y);
            acc.x = fmaf(w0, v0.x, acc.x); acc.y = fmaf(w0, v0.y, acc.y);
            acc.z = fmaf(w0, v0.z, acc.z); acc.w = fmaf(w0, v0.w, acc.w);
            acc.x = fmaf(w1, v1.x, acc.x); acc.y = fmaf(w1, v1.y, acc.y);
            acc.z = fmaf(w1, v1.z, acc.z); acc.w = fmaf(w1, v1.w, acc.w);
            acc.x = fmaf(w2, v2.x, acc.x); acc.y = fmaf(w2, v2.y, acc.y);
            acc.z = fmaf(w2, v2.z, acc.z); acc.w = fmaf(w2, v2.w, acc.w);
            acc.x = fmaf(w3, v3.x, acc.x); acc.y = fmaf(w3, v3.y, acc.y);
            acc.z = fmaf(w3, v3.z, acc.z); acc.w = fmaf(w3, v3.w, acc.w);
        }
        for (; e < end; e++) {
            int2 ed = g_csr[e];
            float w = __int_as_float(ed.y);
            float4 v = *(const float4*)&g_support1[(size_t)ed.x * 64 + c];
            acc.x = fmaf(w, v.x, acc.x); acc.y = fmaf(w, v.y, acc.y);
            acc.z = fmaf(w, v.z, acc.z); acc.w = fmaf(w, v.w, acc.w);
        }
        float4 bb = *(const float4*)&b1[c];
        acc.x = fmaxf(acc.x + bb.x, 0.f);
        acc.y = fmaxf(acc.y + bb.y, 0.f);
        acc.z = fmaxf(acc.z + bb.z, 0.f);
        acc.w = fmaxf(acc.w + bb.w, 0.f);
    }

    float part[16];
    #pragma unroll
    for (int j = 0; j < 16; j++) {
        float s = acc.x * w2t[j][c];
        s = fmaf(acc.y, w2t[j][c + 1], s);
        s = fmaf(acc.z, w2t[j][c + 2], s);
        s = fmaf(acc.w, w2t[j][c + 3], s);
        part[j] = s;
    }
    #pragma unroll
    for (int d = 1; d < 16; d <<= 1) {
        #pragma unroll
        for (int j = 0; j < 16; j++)
            part[j] += __shfl_xor_sync(0xFFFFFFFFu, part[j], d);
    }
    int sub = t & 15;
    if (valid && sub < 4) {
        *(float4*)&g_support2[(size_t)node * 16 + sub * 4] =
            make_float4(part[sub * 4], part[sub * 4 + 1],
                        part[sub * 4 + 2], part[sub * 4 + 3]);
    }
}

// ------------------------------------------------ spMM2 + log_softmax fused
__global__ void spmm2_kernel(const float* __restrict__ b2,
                             float* __restrict__ out, int N) {
    int t = blockIdx.x * blockDim.x + threadIdx.x;
    int node = t >> 2;
    int q = (t & 3) << 2;

    float4 acc = make_float4(0.f, 0.f, 0.f, 0.f);
    if (node < N) {
        int start = node ? g_off[node - 1] : 0;
        int end = g_off[node];
        int e = start;
        for (; e + 4 <= end; e += 4) {
            int2 e0 = g_csr[e], e1 = g_csr[e + 1], e2 = g_csr[e + 2], e3 = g_csr[e + 3];
            float4 v0 = *(const float4*)&g_support2[(size_t)e0.x * 16 + q];
            float4 v1 = *(const float4*)&g_support2[(size_t)e1.x * 16 + q];
            float4 v2 = *(const float4*)&g_support2[(size_t)e2.x * 16 + q];
            float4 v3 = *(const float4*)&g_support2[(size_t)e3.x * 16 + q];
            float w0 = __int_as_float(e0.y), w1 = __int_as_float(e1.y);
            float w2 = __int_as_float(e2.y), w3 = __int_as_float(e3.y);
            acc.x = fmaf(w0, v0.x, acc.x); acc.y = fmaf(w0, v0.y, acc.y);
            acc.z = fmaf(w0, v0.z, acc.z); acc.w = fmaf(w0, v0.w, acc.w);
            acc.x = fmaf(w1, v1.x, acc.x); acc.y = fmaf(w1, v1.y, acc.y);
            acc.z = fmaf(w1, v1.z, acc.z); acc.w = fmaf(w1, v1.w, acc.w);
            acc.x = fmaf(w2, v2.x, acc.x); acc.y = fmaf(w2, v2.y, acc.y);
            acc.z = fmaf(w2, v2.z, acc.z); acc.w = fmaf(w2, v2.w, acc.w);
            acc.x = fmaf(w3, v3.x, acc.x); acc.y = fmaf(w3, v3.y, acc.y);
            acc.z = fmaf(w3, v3.z, acc.z); acc.w = fmaf(w3, v3.w, acc.w);
        }
        for (; e < end; e++) {
            int2 ed = g_csr[e];
            float w = __int_as_float(ed.y);
            float4 v = *(const float4*)&g_support2[(size_t)ed.x * 16 + q];
            acc.x = fmaf(w, v.x, acc.x); acc.y = fmaf(w, v.y, acc.y);
            acc.z = fmaf(w, v.z, acc.z); acc.w = fmaf(w, v.w, acc.w);
        }
        float4 bb = *(const float4*)&b2[q];
        acc.x += bb.x; acc.y += bb.y; acc.z += bb.z; acc.w += bb.w;
    }

    float m = fmaxf(fmaxf(acc.x, acc.y), fmaxf(acc.z, acc.w));
    m = fmaxf(m, __shfl_xor_sync(0xFFFFFFFFu, m, 1));
    m = fmaxf(m, __shfl_xor_sync(0xFFFFFFFFu, m, 2));
    float s = expf(acc.x - m) + expf(acc.y - m) + expf(acc.z - m) + expf(acc.w - m);
    s += __shfl_xor_sync(0xFFFFFFFFu, s, 1);
    s += __shfl_xor_sync(0xFFFFFFFFu, s, 2);
    float lse = m + logf(s);

    if (node < N) {
        *(float4*)&out[(size_t)node * 16 + q] =
            make_float4(acc.x - lse, acc.y - lse, acc.z - lse, acc.w - lse);
    }
}

// ---------------------------------------------------------------- launch
extern "C" void kernel_launch(void* const* d_in, const int* in_sizes, int n_in,
                              void* d_out, int out_size) {
    const float* x    = (const float*)d_in[0];
    const int*   esrc = (const int*)d_in[1];
    const int*   edst = (const int*)d_in[2];
    const float* ev   = (const float*)d_in[3];
    const float* W1   = (const float*)d_in[4];
    const float* b1   = (const float*)d_in[5];
    const float* W2   = (const float*)d_in[6];
    const float* b2   = (const float*)d_in[7];
    float* out = (float*)d_out;

    int E = in_sizes[1];
    int N = in_sizes[0] / 256;

    int eq = (E + 3) / 4;
    int nq = (N + 3) / 4;
    int nb = (N + SCAN_BLK - 1) / SCAN_BLK;

    // CSR build (gemm1 slotted at launch index 3 so ncu profiles it)
    zero_off_kernel<<<(nq + 255) / 256, 256>>>(N);                 // 0
    hist_kernel<<<(eq + 255) / 256, 256>>>(edst, E);               // 1
    scan_a_kernel<<<nb, SCAN_BLK>>>(N);                            // 2
    gemm1_wmma_kernel<<<(N + 127) / 128, 128>>>(x, W1, N);         // 3 <- profiled
    scan_b_kernel<<<1, 1024>>>(nb);                                // 4
    scan_c_kernel<<<nb, SCAN_BLK>>>(N);                            // 5
    scatter_kernel<<<(eq + 255) / 256, 256>>>(esrc, edst, ev, E);  // 6

    // Layer 1 + gemm2 fused
    spmm1_gemm2_kernel<<<(N * 16 + 255) / 256, 256>>>(b1, W2, N);  // 7

    // Layer 2 + log_softmax
    spmm2_kernel<<<(N * 4 + 255) / 256, 256>>>(b2, out, N);        // 8
}